// round 14
// baseline (speedup 1.0000x reference)
#include <cuda_runtime.h>
#include <cstdint>
#include <math.h>

// SpatialGlimpse fused, one-shot blocks, two-phase separable stencil.
// R14: staging via LDG.128(__ldcg) -> STS.128 instead of cp.async.bulk.
// Rationale: bulk-copy path measured at ~2.2 outstanding requests/SM (DRAM
// pinned 2.5-2.8 TB/s across 6/8/12 CTAs/SM); LDG path has ~55/warp MLP.
// OOB handled by predicated zero loads (no tail loops, no mbarriers at all).
// Shape = R13: NT=128, JW=32 all depths, 7168 blocks, 12 CTAs/SM.

static constexpr int BATCH  = 64;
static constexpr int H = 512, W = 512, C = 3;
static constexpr int OUTHW  = 64;
static constexpr int NDEPTH = 3;
static constexpr int ROWFL  = W * C;   // 1536 floats per image row
static constexpr int NT     = 128;
static constexpr int JW     = 32;      // output columns per block (all depths)
static constexpr int IR     = 9;       // input rows per tile (all depths)

// WF = float4s per tile row = exact Phase-A read extent.
// K4: a0max = (3+12*31)&~3 = 372, reads +20 -> 392 floats -> WF=98
// K2: a0max = (3+ 6*31)&~3 = 188, reads +12 -> 200 floats -> WF=50
// K1: a0max = (3+ 3*31)&~3 =  96, reads +12 -> 108 floats -> WF=27
template<int K> struct Cfg;
template<> struct Cfg<1> { static constexpr int TILE_I = 8; static constexpr int WF = 27; static constexpr int NV = 3; };
template<> struct Cfg<2> { static constexpr int TILE_I = 4; static constexpr int WF = 50; static constexpr int NV = 3; };
template<> struct Cfg<4> { static constexpr int TILE_I = 2; static constexpr int WF = 98; static constexpr int NV = 5; };

static constexpr int NBLK4 = BATCH * 32 * 2;   // 4096
static constexpr int NBLK2 = BATCH * 16 * 2;   // 2048
static constexpr int NBLK1 = BATCH * 8 * 2;    // 1024
static constexpr int NBLK  = NBLK4 + NBLK2 + NBLK1;   // 7168

// SMEM floats: tile IR*RF | hs IR*JW float4. Max = K4: 3528 + 1152 = 4680 floats.
static constexpr int SMEM_BYTES = (IR * 4 * Cfg<4>::WF + IR * JW * 4) * 4;   // 18720

// Horizontal weighted sum of one row window (K+1 pixels x 3 channels).
// SH = sub-float4 shift (compile-time so v[] stays in registers).
template<int K, int SH>
__device__ __forceinline__ void hreduce_one(const float* __restrict__ rowp, float wx, float4& h)
{
    constexpr int NV = Cfg<K>::NV;
    const float hx0 = 1.0f - wx;
    float v[4 * NV];
    const float4* rp = reinterpret_cast<const float4*>(rowp);
#pragma unroll
    for (int t = 0; t < NV; t++) {
        float4 q = rp[t];
        v[4*t+0] = q.x; v[4*t+1] = q.y; v[4*t+2] = q.z; v[4*t+3] = q.w;
    }
    float r0 = hx0 * v[SH + 0] + wx * v[SH + 3*K + 0];
    float r1 = hx0 * v[SH + 1] + wx * v[SH + 3*K + 1];
    float r2 = hx0 * v[SH + 2] + wx * v[SH + 3*K + 2];
#pragma unroll
    for (int q = 1; q < K; q++) {
        r0 += v[SH + 3*q + 0];
        r1 += v[SH + 3*q + 1];
        r2 += v[SH + 3*q + 2];
    }
    h.x = r0; h.y = r1; h.z = r2; h.w = 0.0f;
}

template<int K, int D>
__device__ __forceinline__ void glimpse_body(
    const float* __restrict__ img, const float* __restrict__ offs,
    float* __restrict__ out, float* smem, int b, int i0, int j0)
{
    constexpr int TILE_I = Cfg<K>::TILE_I;
    constexpr int WF     = Cfg<K>::WF;
    constexpr int RF     = 4 * WF;             // tile row pitch (floats)
    constexpr int SPAN   = JW * K + 1;         // input pixel span across x
    constexpr int NF     = IR * WF;            // float4s to stage
    constexpr int ITERS  = (NF + NT - 1) / NT;

    float* tile = smem;
    float4* hs  = reinterpret_cast<float4*>(smem + IR * RF);
    const int tid = threadIdx.x;

    // All threads compute geometry in parallel (fp32 ops match reference rounding).
    const float cy = (offs[2*b + 0] + 1.0f) * (H * 0.5f);
    const float cx = (offs[2*b + 1] + 1.0f) * (W * 0.5f);
    const float Ey = cy - (OUTHW * K - 1) * 0.5f;
    const float Ex = cx - (OUTHW * K - 1) * 0.5f;
    const int   y0 = (int)floorf(Ey);
    const int   x0 = (int)floorf(Ex);
    const float wy = Ey - (float)y0;
    const float wx = Ex - (float)x0;

    const int px0     = x0 + j0 * K;
    const int x_hi    = min(px0 + SPAN, W);
    const int start_f = (px0 * 3) & ~3;                      // 16B aligned, >= 0
    const int end_f   = min((x_hi * 3 + 3) & ~3, ROWFL);
    const int validf  = end_f - start_f;                     // multiple of 4
    const int off0    = px0 * 3 - start_f;                   // 0..3
    const int ytop    = y0 + i0 * K;

    // ── Stage: LDG.128 (L2-only) -> STS.128, OOB -> zero. Fully parallel,
    //    high MLP; STS addr = tile + 4*fidx (coalesced, conflict-free). ──
    const float* imgb = img + (size_t)b * H * ROWFL + start_f;
#pragma unroll
    for (int it = 0; it < ITERS; it++) {
        const int fidx = tid + it * NT;
        if (NF % NT == 0 || fidx < NF) {
            const int r = fidx / WF;           // const divisor -> mul/shift
            const int c = fidx - r * WF;
            const int gy = ytop + r;
            float4 v = make_float4(0.f, 0.f, 0.f, 0.f);
            if ((unsigned)gy < (unsigned)H && 4 * c < validf) {
                v = __ldcg(reinterpret_cast<const float4*>(imgb + (size_t)gy * ROWFL) + c);
            }
            *reinterpret_cast<float4*>(tile + 4 * fidx) = v;
        }
    }
    __syncthreads();

    // ── Phase A: horizontal (K+1)-tap sums; 288 items over 128 threads.
    //    Lane word-stride 3K -> conflict-free LDS.128; shift hoisted per thread. ──
    {
        const int jA   = tid & 31;
        const int sidx = off0 + 3 * K * jA;
        const float* colp = tile + (sidx & ~3);
        const int sh = sidx & 3;
#pragma unroll
        for (int it = 0; it < 3; it++) {
            const int r = (tid >> 5) + it * 4;
            if (r < IR) {
                const float* rowp = colp + r * RF;
                float4 h;
                switch (sh) {
                case 0:  hreduce_one<K,0>(rowp, wx, h); break;
                case 1:  hreduce_one<K,1>(rowp, wx, h); break;
                case 2:  hreduce_one<K,2>(rowp, wx, h); break;
                default: hreduce_one<K,3>(rowp, wx, h); break;
                }
                hs[r * JW + jA] = h;
            }
        }
    }
    __syncthreads();

    // ── Phase B: vertical (K+1)-tap over hs. Conflict-free. ──
    constexpr float inv = 1.0f / (K * K);
    const float wy0 = 1.0f - wy;
    for (int o = tid; o < TILE_I * JW; o += NT) {
        const int ti = o >> 5;
        const int jj = o & 31;
        float4 a = hs[(ti * K) * JW + jj];
        float o0 = wy0 * a.x, o1 = wy0 * a.y, o2 = wy0 * a.z;
#pragma unroll
        for (int p = 1; p < K; p++) {
            float4 m = hs[(ti * K + p) * JW + jj];
            o0 += m.x; o1 += m.y; o2 += m.z;
        }
        float4 e = hs[(ti * K + K) * JW + jj];
        o0 += wy * e.x; o1 += wy * e.y; o2 += wy * e.z;

        const size_t ob = (((size_t)b * OUTHW + (i0 + ti)) * OUTHW + (j0 + jj)) * (C * NDEPTH);
        out[ob + 0 * NDEPTH + D] = o0 * inv;
        out[ob + 1 * NDEPTH + D] = o1 * inv;
        out[ob + 2 * NDEPTH + D] = o2 * inv;
    }
}

__global__ __launch_bounds__(NT, 12)
void glimpse_fused(const float* __restrict__ img, const float* __restrict__ offs,
                   float* __restrict__ out)
{
    extern __shared__ float smem[];
    const int bid = blockIdx.x;
    if (bid < NBLK4) {                       // K=4: 64 blocks/image (32 row x 2 col)
        const int b = bid >> 6;
        const int t = bid & 63;
        glimpse_body<4, 2>(img, offs, out, smem, b, (t >> 1) * 2, (t & 1) * JW);
    } else if (bid < NBLK4 + NBLK2) {        // K=2: 32 blocks/image (16 row x 2 col)
        const int r = bid - NBLK4;
        const int b = r >> 5;
        const int t = r & 31;
        glimpse_body<2, 1>(img, offs, out, smem, b, (t >> 1) * 4, (t & 1) * JW);
    } else {                                 // K=1: 16 blocks/image (8 row x 2 col)
        const int r = bid - (NBLK4 + NBLK2);
        const int b = r >> 4;
        const int t = r & 15;
        glimpse_body<1, 0>(img, offs, out, smem, b, (t >> 1) * 8, (t & 1) * JW);
    }
}

extern "C" void kernel_launch(void* const* d_in, const int* in_sizes, int n_in,
                              void* d_out, int out_size)
{
    (void)in_sizes; (void)n_in; (void)out_size;
    const float* img  = (const float*)d_in[0];
    const float* offs = (const float*)d_in[1];
    float* out = (float*)d_out;

    cudaFuncSetAttribute(glimpse_fused, cudaFuncAttributeMaxDynamicSharedMemorySize, SMEM_BYTES);
    glimpse_fused<<<NBLK, NT, SMEM_BYTES>>>(img, offs, out);
}